// round 15
// baseline (speedup 1.0000x reference)
#include <cuda_runtime.h>
#include <cuda_fp16.h>
#include <cstdint>

// Problem dims
#define TT 2048
#define BB 16
#define DD 1024
static constexpr int MROWS = TT * BB;     // 32768
static constexpr int KDIM  = DD;          // 1024
static constexpr int NDIM  = 3 * DD;      // 3072
static constexpr int NTILES = NDIM / 128; // 24

// scan chunking
static constexpr int NCH  = 32;           // chunks along T
static constexpr int CLEN = TT / NCH;     // 64
static constexpr int NCHAN = BB * DD;     // 16384 channels

// ---------------- scratch (device globals: alloc-free rule) ----------------
__device__ __half g_pre16[(size_t)MROWS * NDIM];      // 192 MB (fp16 GEMM out)
__device__ __half g_wh[(size_t)NDIM * KDIM];          // 6 MB  (W^T fp16)
__device__ __half g_a16[(size_t)MROWS * KDIM];        // 64 MB (A fp16)
__device__ float  g_psum[(size_t)MROWS * NTILES * 2]; // 6 MB  (partial LN sums)
__device__ float2 g_stats[(size_t)MROWS];             // 256 KB (rstd, -mu*rstd)
__device__ float  g_P[(size_t)NCH * NCHAN];           // 2 MB
__device__ float  g_S[(size_t)NCH * NCHAN];           // 2 MB
__device__ float  g_H[(size_t)NCH * NCHAN];           // 2 MB

// ---------------- helpers ----------------
__device__ __forceinline__ uint32_t smem_u32(const void* p) {
    uint32_t a;
    asm("{ .reg .u64 t; cvta.to.shared.u64 t, %1; cvt.u32.u64 %0, t; }" : "=r"(a) : "l"(p));
    return a;
}
#define SWZ(o) ((o) ^ (((o) >> 3) & 0x70))

__device__ __forceinline__ void ldsm_x4(uint32_t addr, uint32_t* r) {
    asm volatile("ldmatrix.sync.aligned.m8n8.x4.shared.b16 {%0,%1,%2,%3}, [%4];"
        : "=r"(r[0]), "=r"(r[1]), "=r"(r[2]), "=r"(r[3]) : "r"(addr));
}
__device__ __forceinline__ void mma_f16(float* c, const uint32_t* a, const uint32_t* b) {
    asm volatile("mma.sync.aligned.m16n8k16.row.col.f32.f16.f16.f32 "
        "{%0,%1,%2,%3}, {%4,%5,%6,%7}, {%8,%9}, {%0,%1,%2,%3};"
        : "+f"(c[0]), "+f"(c[1]), "+f"(c[2]), "+f"(c[3])
        : "r"(a[0]), "r"(a[1]), "r"(a[2]), "r"(a[3]), "r"(b[0]), "r"(b[1]));
}
__device__ __forceinline__ void cp_async16(uint32_t saddr, const void* gaddr) {
    asm volatile("cp.async.cg.shared.global [%0], [%1], 16;" :: "r"(saddr), "l"(gaddr));
}
#define CP_COMMIT() asm volatile("cp.async.commit_group;" ::: "memory")
#define CP_WAIT(n)  asm volatile("cp.async.wait_group %0;" :: "n"(n) : "memory")

__device__ __forceinline__ void unpack4(uint2 u, float* v) {
    float2 a = __half22float2(*(__half2*)&u.x);
    float2 b = __half22float2(*(__half2*)&u.y);
    v[0] = a.x; v[1] = a.y; v[2] = b.x; v[3] = b.y;
}

__device__ __forceinline__ float tanh_fast(float x) {
    float r;
    asm("tanh.approx.f32 %0, %1;" : "=f"(r) : "f"(x));
    return r;
}

// ---------------- kernel 1: fused prep (A fp32->fp16  ||  W transpose->fp16) --
static constexpr int A16_BLOCKS = (MROWS * KDIM / 4) / 256;  // 32768
static constexpr int WT_BLOCKS  = (KDIM / 32) * (NDIM / 32); // 3072

__global__ void __launch_bounds__(256) prep_kernel(const float* __restrict__ A,
                                                   const float* __restrict__ W) {
    __shared__ float tile[32][33];
    int tid = threadIdx.x;
    if (blockIdx.x < A16_BLOCKS) {
        size_t idx = (size_t)blockIdx.x * 256 + tid;   // float4 index
        float4 v = ((const float4*)A)[idx];
        __half2 h01 = __floats2half2_rn(v.x, v.y);
        __half2 h23 = __floats2half2_rn(v.z, v.w);
        uint2 u;
        u.x = *(uint32_t*)&h01;
        u.y = *(uint32_t*)&h23;
        ((uint2*)g_a16)[idx] = u;
    } else {
        int bi = blockIdx.x - A16_BLOCKS;
        int k0 = (bi & 31) * 32;          // 32 k-tiles
        int n0 = (bi >> 5) * 32;          // 96 n-tiles
        int tx = tid & 31, ty = tid >> 5; // (32, 8)
#pragma unroll
        for (int i = 0; i < 4; i++) {
            int k = k0 + ty + i * 8;
            tile[ty + i * 8][tx] = W[(size_t)k * NDIM + n0 + tx];
        }
        __syncthreads();
#pragma unroll
        for (int i = 0; i < 4; i++) {
            int n = n0 + ty + i * 8;
            g_wh[(size_t)n * KDIM + k0 + tx] = __float2half_rn(tile[tx][ty + i * 8]);
        }
    }
}

// ---------------- kernel 2: fp16 GEMM (tile 128x128, BK=64, 4 warps 64x64) ---
// 3-stage cp.async pipeline, 2 CTAs/SM for epilogue overlap.
static constexpr int ST_A  = 0;        // 128x64 fp16 = 16KB
static constexpr int ST_B  = 16384;    // 128x64 fp16 = 16KB
static constexpr int STAGE_BYTES = 32768;
static constexpr int GEMM_SMEM = 1024 + 3 * STAGE_BYTES;   // ~97 KB

__global__ void __launch_bounds__(128, 2) gemm_kernel() {
    extern __shared__ char smem_raw[];
    uint32_t s0 = smem_u32(smem_raw);
    uint32_t base = (s0 + 1023) & ~1023u;
    char* smb = smem_raw + (base - s0);

    int tid = threadIdx.x;
    int lane = tid & 31, wid = tid >> 5;      // 4 warps
    int wm = wid & 1, wn = wid >> 1;          // 2 M x 2 N, warp tile 64x64
    int ntile = blockIdx.x;                   // 0..23
    int mtile = blockIdx.y;                   // 0..255
    int m0 = mtile * 128;

    const __half* Bp = g_wh + (size_t)ntile * 128 * KDIM;

    auto issue = [&](int kc, int buf) {
        uint32_t stu = base + buf * STAGE_BYTES;
#pragma unroll
        for (int i = 0; i < 8; i++) {          // A: 1024 16B chunks
            int fid = tid + i * 128;
            int r = fid >> 3, q = fid & 7;
            uint32_t sw = SWZ((uint32_t)(r * 128 + q * 16));
            cp_async16(stu + ST_A + sw, g_a16 + (size_t)(m0 + r) * KDIM + kc * 64 + q * 8);
        }
#pragma unroll
        for (int i = 0; i < 8; i++) {          // B: 1024 chunks
            int fid = tid + i * 128;
            int r = fid >> 3, q = fid & 7;
            uint32_t sw = SWZ((uint32_t)(r * 128 + q * 16));
            cp_async16(stu + ST_B + sw, Bp + (size_t)r * KDIM + kc * 64 + q * 8);
        }
    };

    float acc[4][8][4];
#pragma unroll
    for (int i = 0; i < 4; i++)
#pragma unroll
        for (int j = 0; j < 8; j++)
#pragma unroll
            for (int k = 0; k < 4; k++) acc[i][j][k] = 0.f;

    // lane geometry
    int a_row = wm * 64 + (lane & 15);
    int a_kb  = ((lane >> 4) & 1) * 16;
    int b_row = wn * 64 + (lane & 7) + ((lane >> 4) & 1) * 8;
    int b_kb  = ((lane >> 3) & 1) * 16;

    auto compute = [&](int buf) {
        uint32_t stu = base + buf * STAGE_BYTES;
#pragma unroll
        for (int s = 0; s < 4; s++) {
            uint32_t ah[4][4];
#pragma unroll
            for (int mi = 0; mi < 4; mi++) {
                uint32_t off = (uint32_t)((a_row + mi * 16) * 128 + s * 32 + a_kb);
                ldsm_x4(stu + ST_A + SWZ(off), ah[mi]);
            }
            uint32_t bh[4][4];
#pragma unroll
            for (int nj = 0; nj < 4; nj++) {
                uint32_t off = (uint32_t)((b_row + nj * 16) * 128 + s * 32 + b_kb);
                ldsm_x4(stu + ST_B + SWZ(off), bh[nj]);
            }
#pragma unroll
            for (int mi = 0; mi < 4; mi++)
#pragma unroll
                for (int n8 = 0; n8 < 8; n8++)
                    mma_f16(acc[mi][n8], ah[mi], &bh[n8 >> 1][(n8 & 1) * 2]);
        }
    };

    // prologue: stages 0 and 1 in flight
    issue(0, 0); CP_COMMIT();
    issue(1, 1); CP_COMMIT();

    // main loop: one barrier per iteration
    for (int kc = 0; kc < 16; kc++) {
        if (kc < 15) { CP_WAIT(1); } else { CP_WAIT(0); }
        __syncthreads();
        if (kc + 2 < 16) { issue(kc + 2, (kc + 2) % 3); CP_COMMIT(); }
        compute(kc % 3);
    }

    // ---- epilogue part 1: write pre (fp16) ----
    int g = lane >> 2, t4 = lane & 3;
    __half* outp = g_pre16 + (size_t)(m0 + wm * 64) * NDIM + ntile * 128 + wn * 64;
#pragma unroll
    for (int mi = 0; mi < 4; mi++) {
#pragma unroll
        for (int n8 = 0; n8 < 8; n8++) {
            __half* p0 = outp + (size_t)(mi * 16 + g) * NDIM + n8 * 8 + 2 * t4;
            *(__half2*)p0 = __floats2half2_rn(acc[mi][n8][0], acc[mi][n8][1]);
            *(__half2*)(p0 + (size_t)8 * NDIM) = __floats2half2_rn(acc[mi][n8][2], acc[mi][n8][3]);
        }
    }

    // ---- epilogue part 2: deterministic LN partial sums (from exact fp32 accs) ----
    float rs[8], rq[8];
#pragma unroll
    for (int mi = 0; mi < 4; mi++) {
#pragma unroll
        for (int half = 0; half < 2; half++) {
            float s = 0.f, q = 0.f;
#pragma unroll
            for (int n8 = 0; n8 < 8; n8++) {
#pragma unroll
                for (int e = 0; e < 2; e++) {
                    float v = acc[mi][n8][half * 2 + e];
                    s += v; q += v * v;
                }
            }
            rs[mi * 2 + half] = s;
            rq[mi * 2 + half] = q;
        }
    }
#pragma unroll
    for (int o = 1; o <= 2; o <<= 1) {
#pragma unroll
        for (int k = 0; k < 8; k++) {
            rs[k] += __shfl_xor_sync(0xFFFFFFFFu, rs[k], o);
            rq[k] += __shfl_xor_sync(0xFFFFFFFFu, rq[k], o);
        }
    }
    __syncthreads();   // smem tiles no longer needed
    float* part_s = (float*)smb;            // [2 wn][128 rows]
    float* part_q = part_s + 2 * 128;
    if (t4 == 0) {
#pragma unroll
        for (int k = 0; k < 8; k++) {
            int row = wm * 64 + (k >> 1) * 16 + (k & 1) * 8 + g;
            part_s[wn * 128 + row] = rs[k];
            part_q[wn * 128 + row] = rq[k];
        }
    }
    __syncthreads();
    if (tid < 128) {
        float s = part_s[tid] + part_s[128 + tid];
        float q = part_q[tid] + part_q[128 + tid];
        size_t o = ((size_t)(m0 + tid) * NTILES + ntile) * 2;
        g_psum[o] = s;
        g_psum[o + 1] = q;
    }
}

// ---------------- kernel 3: fold partials -> (rstd, -mu*rstd) ----------------
__global__ void __launch_bounds__(256) musig_kernel() {
    int row = blockIdx.x * 256 + threadIdx.x;
    const float4* p = (const float4*)(g_psum + (size_t)row * NTILES * 2);  // 48 floats = 12 float4
    float s = 0.f, q = 0.f;
#pragma unroll
    for (int i = 0; i < 12; i++) {
        float4 v = p[i];
        s += v.x + v.z;
        q += v.y + v.w;
    }
    float mu = s * (1.0f / NDIM);
    float var = q * (1.0f / NDIM) - mu * mu;
    float rstd = rsqrtf(var + 1e-5f);
    g_stats[row] = make_float2(rstd, -mu * rstd);   // z = v*rstd + (-mu*rstd)
}

// ---------------- kernel 4a: chunk-local scan, 4 ch/thread, 128-thr blocks ---
// LN folded: z = fma(v, st.x, st.y); y = fma(z, ga, be).
// Sigmoid planes use half-scaled ga/be: sigma(y) = fma(tanh(yh), .5, .5).
__global__ void __launch_bounds__(128) scan1_kernel(const float* __restrict__ gamma,
                                                    const float* __restrict__ beta) {
    int gidx = blockIdx.x * 128 + threadIdx.x;  // (c, b, dq)  dq = d/4
    int dq = gidx & 255;
    int rest = gidx >> 8;
    int b = rest & 15;
    int c = rest >> 4;
    int d = dq * 4;
    bool fwd = d < 512;
    int t = fwd ? (c * CLEN) : (TT - 1 - c * CLEN);
    int step = fwd ? 1 : -1;
    float4 ga0 = *(const float4*)(gamma + d);
    float4 be0 = *(const float4*)(beta + d);
    float4 ga1 = *(const float4*)(gamma + d + 1024);
    float4 be1 = *(const float4*)(beta + d + 1024);
    // half-scale the sigmoid-plane constants
#pragma unroll
    for (int j = 0; j < 4; j++) { (&ga0.x)[j] *= 0.5f; (&be0.x)[j] *= 0.5f; }
    float h[4] = {0.f, 0.f, 0.f, 0.f};
    float p[4] = {1.f, 1.f, 1.f, 1.f};
#pragma unroll 4
    for (int i = 0; i < CLEN; i++) {
        int m = t * BB + b;
        float2 st = g_stats[m];
        const __half* prm = g_pre16 + (size_t)m * NDIM + d;
        float v0[4], v1[4];
        unpack4(*(const uint2*)prm, v0);
        unpack4(*(const uint2*)(prm + 1024), v1);
#pragma unroll
        for (int j = 0; j < 4; j++) {
            float z0 = fmaf(v0[j], st.x, st.y);
            float y0h = fmaf(z0, (&ga0.x)[j], (&be0.x)[j]);
            float gg = fmaf(tanh_fast(y0h), 0.5f, 0.5f);
            float a = 1.0f - gg;
            float z1 = fmaf(v1[j], st.x, st.y);
            float y1 = fmaf(z1, (&ga1.x)[j], (&be1.x)[j]);
            h[j] = fmaf(a, h[j], gg * y1);
            p[j] *= a;
        }
        t += step;
    }
    int j0 = ((c * BB + b) << 10) + d;
    *(float4*)(g_P + j0) = make_float4(p[0], p[1], p[2], p[3]);
    *(float4*)(g_S + j0) = make_float4(h[0], h[1], h[2], h[3]);
}

// ---------------- kernel 4b: combine chunk summaries, 4 ch/thread ----------
__global__ void __launch_bounds__(256) scan2_kernel() {
    int cid = blockIdx.x * 256 + threadIdx.x;   // 0..4095: (b, d/4)
    int d = (cid & 255) * 4;
    int b = cid >> 8;
    float h[4] = {0.f, 0.f, 0.f, 0.f};
#pragma unroll
    for (int c = 0; c < NCH; c++) {
        int j = ((c * BB + b) << 10) + d;
        *(float4*)(g_H + j) = make_float4(h[0], h[1], h[2], h[3]);
        float4 pp = *(const float4*)(g_P + j);
        float4 ss = *(const float4*)(g_S + j);
        h[0] = fmaf(pp.x, h[0], ss.x);
        h[1] = fmaf(pp.y, h[1], ss.y);
        h[2] = fmaf(pp.z, h[2], ss.z);
        h[3] = fmaf(pp.w, h[3], ss.w);
    }
}

// ---------------- kernel 4c: apply + fused LN + output mix, 128-thr blocks ---
__global__ void __launch_bounds__(128) scan3_kernel(const float* __restrict__ inp,
                                                    float* __restrict__ out,
                                                    const float* __restrict__ gamma,
                                                    const float* __restrict__ beta) {
    int gidx = blockIdx.x * 128 + threadIdx.x;
    int dq = gidx & 255;
    int rest = gidx >> 8;
    int b = rest & 15;
    int c = rest >> 4;
    int d = dq * 4;
    bool fwd = d < 512;
    int t = fwd ? (c * CLEN) : (TT - 1 - c * CLEN);
    int step = fwd ? 1 : -1;
    float4 ga0 = *(const float4*)(gamma + d);
    float4 be0 = *(const float4*)(beta + d);
    float4 ga1 = *(const float4*)(gamma + d + 1024);
    float4 be1 = *(const float4*)(beta + d + 1024);
    float4 ga2 = *(const float4*)(gamma + d + 2048);
    float4 be2 = *(const float4*)(beta + d + 2048);
    // half-scale the sigmoid-plane constants (planes 0 and 2)
#pragma unroll
    for (int j = 0; j < 4; j++) {
        (&ga0.x)[j] *= 0.5f; (&be0.x)[j] *= 0.5f;
        (&ga2.x)[j] *= 0.5f; (&be2.x)[j] *= 0.5f;
    }
    int j0 = ((c * BB + b) << 10) + d;
    float4 h4 = *(const float4*)(g_H + j0);
    float h[4] = {h4.x, h4.y, h4.z, h4.w};
#pragma unroll 4
    for (int i = 0; i < CLEN; i++) {
        int m = t * BB + b;
        float2 st = g_stats[m];
        const __half* prm = g_pre16 + (size_t)m * NDIM + d;
        float v0[4], v1[4], v2[4];
        unpack4(*(const uint2*)prm, v0);
        unpack4(*(const uint2*)(prm + 1024), v1);
        unpack4(*(const uint2*)(prm + 2048), v2);
        size_t oi = (size_t)m * 1024 + d;
        float4 xi = *(const float4*)(inp + oi);
        float4 r;
#pragma unroll
        for (int j = 0; j < 4; j++) {
            float z0 = fmaf(v0[j], st.x, st.y);
            float y0h = fmaf(z0, (&ga0.x)[j], (&be0.x)[j]);
            float gg = fmaf(tanh_fast(y0h), 0.5f, 0.5f);
            float a = 1.0f - gg;
            float z1 = fmaf(v1[j], st.x, st.y);
            float y1 = fmaf(z1, (&ga1.x)[j], (&be1.x)[j]);
            float z2 = fmaf(v2[j], st.x, st.y);
            float y2h = fmaf(z2, (&ga2.x)[j], (&be2.x)[j]);
            float hg = fmaf(tanh_fast(y2h), 0.5f, 0.5f);
            h[j] = fmaf(a, h[j], gg * y1);
            (&r.x)[j] = fmaf(hg, (&xi.x)[j] - h[j], h[j]);
        }
        *(float4*)(out + oi) = r;
        t += step;
    }
}

// ---------------- launch ----------------
extern "C" void kernel_launch(void* const* d_in, const int* in_sizes, int n_in,
                              void* d_out, int out_size) {
    const float* inp   = (const float*)d_in[0];
    const float* W     = (const float*)d_in[1];
    const float* gamma = (const float*)d_in[2];
    const float* beta  = (const float*)d_in[3];
    float* out = (float*)d_out;

    cudaFuncSetAttribute(gemm_kernel, cudaFuncAttributeMaxDynamicSharedMemorySize, GEMM_SMEM);

    prep_kernel<<<A16_BLOCKS + WT_BLOCKS, 256>>>(inp, W);
    gemm_kernel<<<dim3(24, 256), 128, GEMM_SMEM>>>();
    musig_kernel<<<MROWS / 256, 256>>>();
    scan1_kernel<<<(NCH * NCHAN / 4) / 128, 128>>>(gamma, beta);
    scan2_kernel<<<(NCHAN / 4) / 256, 256>>>();
    scan3_kernel<<<(NCH * NCHAN / 4) / 128, 128>>>(inp, out, gamma, beta);
}

// round 16
// speedup vs baseline: 1.0151x; 1.0151x over previous
#include <cuda_runtime.h>
#include <cuda_fp16.h>
#include <cstdint>

// Problem dims
#define TT 2048
#define BB 16
#define DD 1024
static constexpr int MROWS = TT * BB;     // 32768
static constexpr int KDIM  = DD;          // 1024
static constexpr int NDIM  = 3 * DD;      // 3072
static constexpr int NTILES = NDIM / 128; // 24

// scan chunking
static constexpr int NCH  = 32;           // chunks along T
static constexpr int CLEN = TT / NCH;     // 64
static constexpr int NCHAN = BB * DD;     // 16384 channels

// ---------------- scratch (device globals: alloc-free rule) ----------------
__device__ __half g_pre16[(size_t)MROWS * NDIM];      // 192 MB (fp16 GEMM out)
__device__ __half g_wh[(size_t)NDIM * KDIM];          // 6 MB  (W^T fp16)
__device__ __half g_a16[(size_t)MROWS * KDIM];        // 64 MB (A fp16)
__device__ float  g_psum[(size_t)MROWS * NTILES * 2]; // 6 MB  (partial LN sums)
__device__ float2 g_stats[(size_t)MROWS];             // 256 KB (mu, rstd)
__device__ float  g_P[(size_t)NCH * NCHAN];           // 2 MB
__device__ float  g_S[(size_t)NCH * NCHAN];           // 2 MB
__device__ float  g_H[(size_t)NCH * NCHAN];           // 2 MB

// ---------------- helpers ----------------
__device__ __forceinline__ uint32_t smem_u32(const void* p) {
    uint32_t a;
    asm("{ .reg .u64 t; cvta.to.shared.u64 t, %1; cvt.u32.u64 %0, t; }" : "=r"(a) : "l"(p));
    return a;
}
#define SWZ(o) ((o) ^ (((o) >> 3) & 0x70))

__device__ __forceinline__ void ldsm_x4(uint32_t addr, uint32_t* r) {
    asm volatile("ldmatrix.sync.aligned.m8n8.x4.shared.b16 {%0,%1,%2,%3}, [%4];"
        : "=r"(r[0]), "=r"(r[1]), "=r"(r[2]), "=r"(r[3]) : "r"(addr));
}
__device__ __forceinline__ void mma_f16(float* c, const uint32_t* a, const uint32_t* b) {
    asm volatile("mma.sync.aligned.m16n8k16.row.col.f32.f16.f16.f32 "
        "{%0,%1,%2,%3}, {%4,%5,%6,%7}, {%8,%9}, {%0,%1,%2,%3};"
        : "+f"(c[0]), "+f"(c[1]), "+f"(c[2]), "+f"(c[3])
        : "r"(a[0]), "r"(a[1]), "r"(a[2]), "r"(a[3]), "r"(b[0]), "r"(b[1]));
}
__device__ __forceinline__ void cp_async16(uint32_t saddr, const void* gaddr) {
    asm volatile("cp.async.cg.shared.global [%0], [%1], 16;" :: "r"(saddr), "l"(gaddr));
}
#define CP_COMMIT() asm volatile("cp.async.commit_group;" ::: "memory")
#define CP_WAIT(n)  asm volatile("cp.async.wait_group %0;" :: "n"(n) : "memory")

__device__ __forceinline__ void unpack4(uint2 u, float* v) {
    float2 a = __half22float2(*(__half2*)&u.x);
    float2 b = __half22float2(*(__half2*)&u.y);
    v[0] = a.x; v[1] = a.y; v[2] = b.x; v[3] = b.y;
}

__device__ __forceinline__ float tanh_fast(float x) {
    float r;
    asm("tanh.approx.f32 %0, %1;" : "=f"(r) : "f"(x));
    return r;
}
// sigmoid(x) = 0.5*tanh(x/2) + 0.5   (single MUFU)
__device__ __forceinline__ float sigmoid_fast(float x) {
    return fmaf(tanh_fast(0.5f * x), 0.5f, 0.5f);
}

// ---------------- kernel 1: fused prep (A fp32->fp16  ||  W transpose->fp16) --
static constexpr int A16_BLOCKS = (MROWS * KDIM / 4) / 256;  // 32768
static constexpr int WT_BLOCKS  = (KDIM / 32) * (NDIM / 32); // 3072

__global__ void __launch_bounds__(256) prep_kernel(const float* __restrict__ A,
                                                   const float* __restrict__ W) {
    __shared__ float tile[32][33];
    int tid = threadIdx.x;
    if (blockIdx.x < A16_BLOCKS) {
        size_t idx = (size_t)blockIdx.x * 256 + tid;   // float4 index
        float4 v = ((const float4*)A)[idx];
        __half2 h01 = __floats2half2_rn(v.x, v.y);
        __half2 h23 = __floats2half2_rn(v.z, v.w);
        uint2 u;
        u.x = *(uint32_t*)&h01;
        u.y = *(uint32_t*)&h23;
        ((uint2*)g_a16)[idx] = u;
    } else {
        int bi = blockIdx.x - A16_BLOCKS;
        int k0 = (bi & 31) * 32;          // 32 k-tiles
        int n0 = (bi >> 5) * 32;          // 96 n-tiles
        int tx = tid & 31, ty = tid >> 5; // (32, 8)
#pragma unroll
        for (int i = 0; i < 4; i++) {
            int k = k0 + ty + i * 8;
            tile[ty + i * 8][tx] = W[(size_t)k * NDIM + n0 + tx];
        }
        __syncthreads();
#pragma unroll
        for (int i = 0; i < 4; i++) {
            int n = n0 + ty + i * 8;
            g_wh[(size_t)n * KDIM + k0 + tx] = __float2half_rn(tile[tx][ty + i * 8]);
        }
    }
}

// ---------------- kernel 2: fp16 GEMM (tile 128x128, BK=64, 4 warps 64x64) ---
// 3-stage cp.async pipeline, 2 CTAs/SM for epilogue overlap.
static constexpr int ST_A  = 0;        // 128x64 fp16 = 16KB
static constexpr int ST_B  = 16384;    // 128x64 fp16 = 16KB
static constexpr int STAGE_BYTES = 32768;
static constexpr int GEMM_SMEM = 1024 + 3 * STAGE_BYTES;   // ~97 KB

__global__ void __launch_bounds__(128, 2) gemm_kernel() {
    extern __shared__ char smem_raw[];
    uint32_t s0 = smem_u32(smem_raw);
    uint32_t base = (s0 + 1023) & ~1023u;
    char* smb = smem_raw + (base - s0);

    int tid = threadIdx.x;
    int lane = tid & 31, wid = tid >> 5;      // 4 warps
    int wm = wid & 1, wn = wid >> 1;          // 2 M x 2 N, warp tile 64x64
    int ntile = blockIdx.x;                   // 0..23
    int mtile = blockIdx.y;                   // 0..255
    int m0 = mtile * 128;

    const __half* Bp = g_wh + (size_t)ntile * 128 * KDIM;

    auto issue = [&](int kc, int buf) {
        uint32_t stu = base + buf * STAGE_BYTES;
#pragma unroll
        for (int i = 0; i < 8; i++) {          // A: 1024 16B chunks
            int fid = tid + i * 128;
            int r = fid >> 3, q = fid & 7;
            uint32_t sw = SWZ((uint32_t)(r * 128 + q * 16));
            cp_async16(stu + ST_A + sw, g_a16 + (size_t)(m0 + r) * KDIM + kc * 64 + q * 8);
        }
#pragma unroll
        for (int i = 0; i < 8; i++) {          // B: 1024 chunks
            int fid = tid + i * 128;
            int r = fid >> 3, q = fid & 7;
            uint32_t sw = SWZ((uint32_t)(r * 128 + q * 16));
            cp_async16(stu + ST_B + sw, Bp + (size_t)r * KDIM + kc * 64 + q * 8);
        }
    };

    float acc[4][8][4];
#pragma unroll
    for (int i = 0; i < 4; i++)
#pragma unroll
        for (int j = 0; j < 8; j++)
#pragma unroll
            for (int k = 0; k < 4; k++) acc[i][j][k] = 0.f;

    // lane geometry
    int a_row = wm * 64 + (lane & 15);
    int a_kb  = ((lane >> 4) & 1) * 16;
    int b_row = wn * 64 + (lane & 7) + ((lane >> 4) & 1) * 8;
    int b_kb  = ((lane >> 3) & 1) * 16;

    auto compute = [&](int buf) {
        uint32_t stu = base + buf * STAGE_BYTES;
#pragma unroll
        for (int s = 0; s < 4; s++) {
            uint32_t ah[4][4];
#pragma unroll
            for (int mi = 0; mi < 4; mi++) {
                uint32_t off = (uint32_t)((a_row + mi * 16) * 128 + s * 32 + a_kb);
                ldsm_x4(stu + ST_A + SWZ(off), ah[mi]);
            }
            uint32_t bh[4][4];
#pragma unroll
            for (int nj = 0; nj < 4; nj++) {
                uint32_t off = (uint32_t)((b_row + nj * 16) * 128 + s * 32 + b_kb);
                ldsm_x4(stu + ST_B + SWZ(off), bh[nj]);
            }
#pragma unroll
            for (int mi = 0; mi < 4; mi++)
#pragma unroll
                for (int n8 = 0; n8 < 8; n8++)
                    mma_f16(acc[mi][n8], ah[mi], &bh[n8 >> 1][(n8 & 1) * 2]);
        }
    };

    // prologue: stages 0 and 1 in flight
    issue(0, 0); CP_COMMIT();
    issue(1, 1); CP_COMMIT();

    // main loop: one barrier per iteration
    for (int kc = 0; kc < 16; kc++) {
        if (kc < 15) { CP_WAIT(1); } else { CP_WAIT(0); }
        __syncthreads();
        if (kc + 2 < 16) { issue(kc + 2, (kc + 2) % 3); CP_COMMIT(); }
        compute(kc % 3);
    }

    // ---- epilogue part 1: write pre (fp16) ----
    int g = lane >> 2, t4 = lane & 3;
    __half* outp = g_pre16 + (size_t)(m0 + wm * 64) * NDIM + ntile * 128 + wn * 64;
#pragma unroll
    for (int mi = 0; mi < 4; mi++) {
#pragma unroll
        for (int n8 = 0; n8 < 8; n8++) {
            __half* p0 = outp + (size_t)(mi * 16 + g) * NDIM + n8 * 8 + 2 * t4;
            *(__half2*)p0 = __floats2half2_rn(acc[mi][n8][0], acc[mi][n8][1]);
            *(__half2*)(p0 + (size_t)8 * NDIM) = __floats2half2_rn(acc[mi][n8][2], acc[mi][n8][3]);
        }
    }

    // ---- epilogue part 2: deterministic LN partial sums (from exact fp32 accs) ----
    float rs[8], rq[8];
#pragma unroll
    for (int mi = 0; mi < 4; mi++) {
#pragma unroll
        for (int half = 0; half < 2; half++) {
            float s = 0.f, q = 0.f;
#pragma unroll
            for (int n8 = 0; n8 < 8; n8++) {
#pragma unroll
                for (int e = 0; e < 2; e++) {
                    float v = acc[mi][n8][half * 2 + e];
                    s += v; q += v * v;
                }
            }
            rs[mi * 2 + half] = s;
            rq[mi * 2 + half] = q;
        }
    }
#pragma unroll
    for (int o = 1; o <= 2; o <<= 1) {
#pragma unroll
        for (int k = 0; k < 8; k++) {
            rs[k] += __shfl_xor_sync(0xFFFFFFFFu, rs[k], o);
            rq[k] += __shfl_xor_sync(0xFFFFFFFFu, rq[k], o);
        }
    }
    __syncthreads();   // smem tiles no longer needed
    float* part_s = (float*)smb;            // [2 wn][128 rows]
    float* part_q = part_s + 2 * 128;
    if (t4 == 0) {
#pragma unroll
        for (int k = 0; k < 8; k++) {
            int row = wm * 64 + (k >> 1) * 16 + (k & 1) * 8 + g;
            part_s[wn * 128 + row] = rs[k];
            part_q[wn * 128 + row] = rq[k];
        }
    }
    __syncthreads();
    if (tid < 128) {
        float s = part_s[tid] + part_s[128 + tid];
        float q = part_q[tid] + part_q[128 + tid];
        size_t o = ((size_t)(m0 + tid) * NTILES + ntile) * 2;
        g_psum[o] = s;
        g_psum[o + 1] = q;
    }
}

// ---------------- kernel 3: fold partials -> (mu, rstd), vectorized ----------
__global__ void __launch_bounds__(256) musig_kernel() {
    int row = blockIdx.x * 256 + threadIdx.x;
    const float4* p = (const float4*)(g_psum + (size_t)row * NTILES * 2);  // 48 floats = 12 float4
    float s = 0.f, q = 0.f;
#pragma unroll
    for (int i = 0; i < 12; i++) {
        float4 v = p[i];
        s += v.x + v.z;
        q += v.y + v.w;
    }
    float mu = s * (1.0f / NDIM);
    float var = q * (1.0f / NDIM) - mu * mu;
    g_stats[row] = make_float2(mu, rsqrtf(var + 1e-5f));
}

// ---------------- kernel 4a: chunk-local scan, 4 ch/thread, 128-thr blocks ---
__global__ void __launch_bounds__(128) scan1_kernel(const float* __restrict__ gamma,
                                                    const float* __restrict__ beta) {
    int gidx = blockIdx.x * 128 + threadIdx.x;  // (c, b, dq)  dq = d/4
    int dq = gidx & 255;
    int rest = gidx >> 8;
    int b = rest & 15;
    int c = rest >> 4;
    int d = dq * 4;
    bool fwd = d < 512;
    int t = fwd ? (c * CLEN) : (TT - 1 - c * CLEN);
    int step = fwd ? 1 : -1;
    float4 ga0 = *(const float4*)(gamma + d);
    float4 be0 = *(const float4*)(beta + d);
    float4 ga1 = *(const float4*)(gamma + d + 1024);
    float4 be1 = *(const float4*)(beta + d + 1024);
    float h[4] = {0.f, 0.f, 0.f, 0.f};
    float p[4] = {1.f, 1.f, 1.f, 1.f};
#pragma unroll 4
    for (int i = 0; i < CLEN; i++) {
        int m = t * BB + b;
        float2 st = g_stats[m];
        const __half* prm = g_pre16 + (size_t)m * NDIM + d;
        float v0[4], v1[4];
        unpack4(*(const uint2*)prm, v0);
        unpack4(*(const uint2*)(prm + 1024), v1);
#pragma unroll
        for (int j = 0; j < 4; j++) {
            float y0 = (v0[j] - st.x) * st.y * (&ga0.x)[j] + (&be0.x)[j];
            float y1 = (v1[j] - st.x) * st.y * (&ga1.x)[j] + (&be1.x)[j];
            float gg = sigmoid_fast(y0);
            float a = 1.0f - gg;
            h[j] = fmaf(a, h[j], gg * y1);
            p[j] *= a;
        }
        t += step;
    }
    int j0 = ((c * BB + b) << 10) + d;
    *(float4*)(g_P + j0) = make_float4(p[0], p[1], p[2], p[3]);
    *(float4*)(g_S + j0) = make_float4(h[0], h[1], h[2], h[3]);
}

// ---------------- kernel 4b: combine chunk summaries, 4 ch/thread ----------
__global__ void __launch_bounds__(256) scan2_kernel() {
    int cid = blockIdx.x * 256 + threadIdx.x;   // 0..4095: (b, d/4)
    int d = (cid & 255) * 4;
    int b = cid >> 8;
    float h[4] = {0.f, 0.f, 0.f, 0.f};
#pragma unroll
    for (int c = 0; c < NCH; c++) {
        int j = ((c * BB + b) << 10) + d;
        *(float4*)(g_H + j) = make_float4(h[0], h[1], h[2], h[3]);
        float4 pp = *(const float4*)(g_P + j);
        float4 ss = *(const float4*)(g_S + j);
        h[0] = fmaf(pp.x, h[0], ss.x);
        h[1] = fmaf(pp.y, h[1], ss.y);
        h[2] = fmaf(pp.z, h[2], ss.z);
        h[3] = fmaf(pp.w, h[3], ss.w);
    }
}

// ---------------- kernel 4c: apply + fused LN + output mix, 4 ch/thread ------
__global__ void __launch_bounds__(256) scan3_kernel(const float* __restrict__ inp,
                                                    float* __restrict__ out,
                                                    const float* __restrict__ gamma,
                                                    const float* __restrict__ beta) {
    int gidx = blockIdx.x * 256 + threadIdx.x;
    int dq = gidx & 255;
    int rest = gidx >> 8;
    int b = rest & 15;
    int c = rest >> 4;
    int d = dq * 4;
    bool fwd = d < 512;
    int t = fwd ? (c * CLEN) : (TT - 1 - c * CLEN);
    int step = fwd ? 1 : -1;
    float4 ga0 = *(const float4*)(gamma + d);
    float4 be0 = *(const float4*)(beta + d);
    float4 ga1 = *(const float4*)(gamma + d + 1024);
    float4 be1 = *(const float4*)(beta + d + 1024);
    float4 ga2 = *(const float4*)(gamma + d + 2048);
    float4 be2 = *(const float4*)(beta + d + 2048);
    int j0 = ((c * BB + b) << 10) + d;
    float4 h4 = *(const float4*)(g_H + j0);
    float h[4] = {h4.x, h4.y, h4.z, h4.w};
#pragma unroll 4
    for (int i = 0; i < CLEN; i++) {
        int m = t * BB + b;
        float2 st = g_stats[m];
        const __half* prm = g_pre16 + (size_t)m * NDIM + d;
        float v0[4], v1[4], v2[4];
        unpack4(*(const uint2*)prm, v0);
        unpack4(*(const uint2*)(prm + 1024), v1);
        unpack4(*(const uint2*)(prm + 2048), v2);
        size_t oi = (size_t)m * 1024 + d;
        float4 xi = *(const float4*)(inp + oi);
        float4 r;
#pragma unroll
        for (int j = 0; j < 4; j++) {
            float y0 = (v0[j] - st.x) * st.y * (&ga0.x)[j] + (&be0.x)[j];
            float y1 = (v1[j] - st.x) * st.y * (&ga1.x)[j] + (&be1.x)[j];
            float y2 = (v2[j] - st.x) * st.y * (&ga2.x)[j] + (&be2.x)[j];
            float gg = sigmoid_fast(y0);
            float a = 1.0f - gg;
            float hg = sigmoid_fast(y2);
            h[j] = fmaf(a, h[j], gg * y1);
            (&r.x)[j] = fmaf(hg, (&xi.x)[j] - h[j], h[j]);
        }
        *(float4*)(out + oi) = r;
        t += step;
    }
}

// ---------------- launch ----------------
extern "C" void kernel_launch(void* const* d_in, const int* in_sizes, int n_in,
                              void* d_out, int out_size) {
    const float* inp   = (const float*)d_in[0];
    const float* W     = (const float*)d_in[1];
    const float* gamma = (const float*)d_in[2];
    const float* beta  = (const float*)d_in[3];
    float* out = (float*)d_out;

    cudaFuncSetAttribute(gemm_kernel, cudaFuncAttributeMaxDynamicSharedMemorySize, GEMM_SMEM);

    prep_kernel<<<A16_BLOCKS + WT_BLOCKS, 256>>>(inp, W);
    gemm_kernel<<<dim3(24, 256), 128, GEMM_SMEM>>>();
    musig_kernel<<<MROWS / 256, 256>>>();
    scan1_kernel<<<(NCH * NCHAN / 4) / 128, 128>>>(gamma, beta);
    scan2_kernel<<<(NCHAN / 4) / 256, 256>>>();
    scan3_kernel<<<(NCH * NCHAN / 4) / 256, 256>>>(inp, out, gamma, beta);
}